// round 10
// baseline (speedup 1.0000x reference)
#include <cuda_runtime.h>

#define Bb 64
#define NNODE 128
#define NE 4096
#define NP 2048
#define DIN 512
#define DG 256
#define EF 256
#define HIDDEN 512

#define TM 32
#define CIW 516     // row stride (floats) for ci / hid tiles
#define WSW 260     // row stride (floats) for W1 k-major tile

// Scratch: m1 [B*N*512], h [B*N*256], m2 [B*N*256], emb [B*N*256]
__device__ float g_scratch[(size_t)Bb * NNODE * DIN + 3 * (size_t)Bb * NNODE * DG];

__global__ void zero_kernel(float* p, int n) {
    int i = blockIdx.x * blockDim.x + threadIdx.x;
    if (i < n) p[i] = 0.f;
}

// m[b, dst] += x[b, src] over edges. One warp per edge.
__global__ void scatter_kernel(const float* __restrict__ x, const int* __restrict__ ei,
                               float* __restrict__ m, int dim) {
    int gw = (blockIdx.x * blockDim.x + threadIdx.x) >> 5;
    int lane = threadIdx.x & 31;
    if (gw >= Bb * NE) return;
    int b = gw / NE;
    int e = gw - b * NE;
    int src = ei[(size_t)b * 2 * NE + e];
    int dst = ei[(size_t)b * 2 * NE + NE + e];
    const float* xs = x + ((size_t)b * NNODE + src) * dim;
    float* md = m + ((size_t)b * NNODE + dst) * dim;
    for (int k = lane; k < dim; k += 32) atomicAdd(md + k, xs[k]);
}

// C = relu((A1 + A2) @ W), A row-major [M,K], W [K,N]. 64x64 tiles, 4x4/thread.
__global__ void __launch_bounds__(256) gemm_add_relu(
    const float* __restrict__ A1, const float* __restrict__ A2,
    const float* __restrict__ W, float* __restrict__ C,
    int M, int N, int K) {
    __shared__ float As[16][68];
    __shared__ float Bs[16][68];
    int t = threadIdx.x;
    int m0 = blockIdx.y * 64, n0 = blockIdx.x * 64;
    int ty = t >> 4, tx = t & 15;
    int ar = t >> 2, ak = (t & 3) << 2;
    int br = t >> 4, bc = (t & 15) << 2;
    float acc[4][4] = {};
    for (int k0 = 0; k0 < K; k0 += 16) {
        float4 a1 = *(const float4*)(A1 + (size_t)(m0 + ar) * K + k0 + ak);
        float4 a2 = *(const float4*)(A2 + (size_t)(m0 + ar) * K + k0 + ak);
        As[ak + 0][ar] = a1.x + a2.x;
        As[ak + 1][ar] = a1.y + a2.y;
        As[ak + 2][ar] = a1.z + a2.z;
        As[ak + 3][ar] = a1.w + a2.w;
        *(float4*)&Bs[br][bc] = *(const float4*)(W + (size_t)(k0 + br) * N + n0 + bc);
        __syncthreads();
#pragma unroll
        for (int k = 0; k < 16; k++) {
            float4 a = *(const float4*)&As[k][ty << 2];
            float4 bq = *(const float4*)&Bs[k][tx << 2];
            float av[4] = {a.x, a.y, a.z, a.w};
            float bv[4] = {bq.x, bq.y, bq.z, bq.w};
#pragma unroll
            for (int i = 0; i < 4; i++)
#pragma unroll
                for (int j = 0; j < 4; j++) acc[i][j] += av[i] * bv[j];
        }
        __syncthreads();
    }
#pragma unroll
    for (int i = 0; i < 4; i++)
#pragma unroll
        for (int j = 0; j < 4; j++) {
            float v = acc[i][j];
            C[(size_t)(m0 + (ty << 2) + i) * N + n0 + (tx << 2) + j] = v > 0.f ? v : 0.f;
        }
}

// Fused pair classifier: gather ci tile -> 3x (GEMM1+bias+relu -> GEMM2+bias).
// 256 threads, TM=32 pairs per block. ~194KB dynamic SMEM.
__global__ void __launch_bounds__(256) classifier_kernel(
    const float* __restrict__ emb, const int* __restrict__ pairs,
    const float* __restrict__ inter,
    const float* __restrict__ W1_0, const float* __restrict__ b1_0,
    const float* __restrict__ W2_0, const float* __restrict__ b2_0,
    const float* __restrict__ W1_1, const float* __restrict__ b1_1,
    const float* __restrict__ W2_1, const float* __restrict__ b2_1,
    const float* __restrict__ W1_2, const float* __restrict__ b1_2,
    const float* __restrict__ W2_2, const float* __restrict__ b2_2,
    float* __restrict__ out) {
    extern __shared__ float sm[];
    float* ci = sm;                       // TM * CIW
    float* hid = sm + TM * CIW;           // TM * CIW
    float* wbuf = sm + 2 * TM * CIW;      // 64*WSW (GEMM1 tile) / W2^T (GEMM2)

    int t = threadIdx.x;
    int gp0 = blockIdx.x * TM;

    // ---- gather ci = [emb[i0]+emb[i1] | inter[i0,i1]] ----
    {
        int r = t >> 3, j8 = t & 7;
        int gp = gp0 + r;
        int b = gp / NP, pi = gp - b * NP;
        int i0 = pairs[((size_t)b * NP + pi) * 2 + 0];
        int i1 = pairs[((size_t)b * NP + pi) * 2 + 1];
        const float4* e0 = (const float4*)(emb + ((size_t)b * NNODE + i0) * DG);
        const float4* e1 = (const float4*)(emb + ((size_t)b * NNODE + i1) * DG);
        const float4* ef = (const float4*)(inter + (((size_t)b * NNODE + i0) * NNODE + i1) * EF);
        float4* crow = (float4*)(ci + r * CIW);
        for (int i = j8; i < 64; i += 8) {
            float4 a = e0[i], c = e1[i];
            a.x += c.x; a.y += c.y; a.z += c.z; a.w += c.w;
            crow[i] = a;
            crow[64 + i] = ef[i];
        }
    }
    __syncthreads();

    const float* W1s[3] = {W1_0, W1_1, W1_2};
    const float* b1s[3] = {b1_0, b1_1, b1_2};
    const float* W2s[3] = {W2_0, W2_1, W2_2};
    const float* b2s[3] = {b2_0, b2_1, b2_2};
    const int outw[3] = {6, 5, 14};
    const int outoff[3] = {0, 6, 11};

    int rg = t >> 5;        // 0..7 -> rows 4*rg..4*rg+3
    int cg = t & 31;        // 0..31
    int c0 = cg << 2;       // cols c0..c0+3 and c0+128..c0+131 within 256-chunk

    for (int head = 0; head < 3; head++) {
        const float* W1 = W1s[head];
        const float* b1 = b1s[head];
        // ---- GEMM1: hid = relu(ci @ W1 + b1), N-chunks of 256, K-chunks of 64 ----
        for (int nc = 0; nc < HIDDEN; nc += 256) {
            float acc[4][8];
#pragma unroll
            for (int i = 0; i < 4; i++)
#pragma unroll
                for (int j = 0; j < 8; j++) acc[i][j] = 0.f;
            for (int kc = 0; kc < DIN; kc += 64) {
                // load W1[kc..kc+63][nc..nc+255] k-major into wbuf
#pragma unroll
                for (int i = 0; i < 16; i++) {
                    int s = t + (i << 8);
                    int k = s >> 6, cq = (s & 63) << 2;
                    *(float4*)&wbuf[k * WSW + cq] =
                        *(const float4*)(W1 + (size_t)(kc + k) * HIDDEN + nc + cq);
                }
                __syncthreads();
                const float* cb = ci + (rg << 2) * CIW + kc;
#pragma unroll 2
                for (int kk = 0; kk < 64; kk += 4) {
                    float ar[4][4];
#pragma unroll
                    for (int i = 0; i < 4; i++)
                        *(float4*)ar[i] = *(const float4*)(cb + i * CIW + kk);
#pragma unroll
                    for (int dk = 0; dk < 4; dk++) {
                        float4 w0 = *(const float4*)&wbuf[(kk + dk) * WSW + c0];
                        float4 w1 = *(const float4*)&wbuf[(kk + dk) * WSW + c0 + 128];
                        float wv[8] = {w0.x, w0.y, w0.z, w0.w, w1.x, w1.y, w1.z, w1.w};
#pragma unroll
                        for (int i = 0; i < 4; i++) {
                            float a = ar[i][dk];
#pragma unroll
                            for (int j = 0; j < 8; j++) acc[i][j] += a * wv[j];
                        }
                    }
                }
                __syncthreads();
            }
            // epilogue: bias + relu -> hid
#pragma unroll
            for (int j = 0; j < 8; j++) {
                int col = nc + c0 + ((j < 4) ? j : (124 + j));
                float bv = b1[col];
#pragma unroll
                for (int i = 0; i < 4; i++) {
                    float v = acc[i][j] + bv;
                    hid[((rg << 2) + i) * CIW + col] = v > 0.f ? v : 0.f;
                }
            }
        }
        __syncthreads();

        // ---- GEMM2: out = hid @ W2 + b2 ----
        int ow = outw[head];
        const float* W2 = W2s[head];
        for (int idx = t; idx < HIDDEN * ow; idx += 256) {
            int k = idx / ow, c = idx - k * ow;
            wbuf[c * CIW + k] = W2[idx];   // W2^T, row stride CIW
        }
        __syncthreads();
        {
            int r = t >> 3, c8 = t & 7;
            const float* hrow = hid + r * CIW;
            int gp = gp0 + r;
            const float* b2 = b2s[head];
            for (int c = c8; c < ow; c += 8) {
                const float* wcol = wbuf + c * CIW;
                float s = 0.f;
#pragma unroll 4
                for (int k = 0; k < HIDDEN; k += 4) {
                    float4 h4 = *(const float4*)(hrow + k);
                    float4 w4 = *(const float4*)(wcol + k);
                    s += h4.x * w4.x + h4.y * w4.y + h4.z * w4.z + h4.w * w4.w;
                }
                out[(size_t)gp * 25 + outoff[head] + c] = s + b2[c];
            }
        }
        __syncthreads();
    }
}

static const int CLS_SMEM = (2 * TM * CIW + 64 * WSW) * 4;   // 198656 bytes

extern "C" void kernel_launch(void* const* d_in, const int* in_sizes, int n_in,
                              void* d_out, int out_size) {
    const float* obj   = (const float*)d_in[0];
    const int*   ei    = (const int*)d_in[1];
    const int*   pairs = (const int*)d_in[2];
    const float* inter = (const float*)d_in[3];
    const float* Wg1   = (const float*)d_in[4];
    const float* Wg2   = (const float*)d_in[5];
    float* out = (float*)d_out;

    float* scratch = nullptr;
    cudaGetSymbolAddress((void**)&scratch, g_scratch);
    float* m1  = scratch;
    float* h   = m1 + (size_t)Bb * NNODE * DIN;
    float* m2  = h  + (size_t)Bb * NNODE * DG;
    float* emb = m2 + (size_t)Bb * NNODE * DG;

    int nm1 = Bb * NNODE * DIN;
    int nm2 = Bb * NNODE * DG;
    zero_kernel<<<(nm1 + 255) / 256, 256>>>(m1, nm1);
    zero_kernel<<<(nm2 + 255) / 256, 256>>>(m2, nm2);

    int scatter_blocks = (Bb * NE * 32) / 256;
    scatter_kernel<<<scatter_blocks, 256>>>(obj, ei, m1, DIN);

    gemm_add_relu<<<dim3(DG / 64, (Bb * NNODE) / 64), 256>>>(m1, obj, Wg1, h,
                                                             Bb * NNODE, DG, DIN);
    scatter_kernel<<<scatter_blocks, 256>>>(h, ei, m2, DG);
    gemm_add_relu<<<dim3(DG / 64, (Bb * NNODE) / 64), 256>>>(m2, h, Wg2, emb,
                                                             Bb * NNODE, DG, DG);

    cudaFuncSetAttribute((const void*)classifier_kernel,
                         cudaFuncAttributeMaxDynamicSharedMemorySize, CLS_SMEM);
    classifier_kernel<<<(Bb * NP) / TM, 256, CLS_SMEM>>>(
        emb, pairs, inter,
        (const float*)d_in[6],  (const float*)d_in[7],  (const float*)d_in[8],  (const float*)d_in[9],
        (const float*)d_in[10], (const float*)d_in[11], (const float*)d_in[12], (const float*)d_in[13],
        (const float*)d_in[14], (const float*)d_in[15], (const float*)d_in[16], (const float*)d_in[17],
        out);
}

// round 11
// speedup vs baseline: 1.0017x; 1.0017x over previous
#include <cuda_runtime.h>

#define Bb 64
#define NNODE 128
#define NE 4096
#define NP 2048
#define DIN 512
#define DG 256
#define EF 256
#define HIDDEN 512

#define TM 32
#define CIW 516     // row stride (floats) for ci / hid tiles
#define WSW 260     // row stride (floats) for W1 k-major tile

// Scratch: m1 [B*N*512], h [B*N*256], m2 [B*N*256], emb [B*N*256]
__device__ float g_scratch[(size_t)Bb * NNODE * DIN + 3 * (size_t)Bb * NNODE * DG];

__global__ void zero_kernel(float* p, int n) {
    int i = blockIdx.x * blockDim.x + threadIdx.x;
    if (i < n) p[i] = 0.f;
}

// m[b, dst] += x[b, src] over edges. One warp per edge.
__global__ void scatter_kernel(const float* __restrict__ x, const int* __restrict__ ei,
                               float* __restrict__ m, int dim) {
    int gw = (blockIdx.x * blockDim.x + threadIdx.x) >> 5;
    int lane = threadIdx.x & 31;
    if (gw >= Bb * NE) return;
    int b = gw / NE;
    int e = gw - b * NE;
    int src = ei[(size_t)b * 2 * NE + e];
    int dst = ei[(size_t)b * 2 * NE + NE + e];
    const float* xs = x + ((size_t)b * NNODE + src) * dim;
    float* md = m + ((size_t)b * NNODE + dst) * dim;
    for (int k = lane; k < dim; k += 32) atomicAdd(md + k, xs[k]);
}

// C = relu((A1 + A2) @ W), A row-major [M,K], W [K,N]. 64x64 tiles, 4x4/thread.
__global__ void __launch_bounds__(256) gemm_add_relu(
    const float* __restrict__ A1, const float* __restrict__ A2,
    const float* __restrict__ W, float* __restrict__ C,
    int M, int N, int K) {
    __shared__ float As[16][68];
    __shared__ float Bs[16][68];
    int t = threadIdx.x;
    int m0 = blockIdx.y * 64, n0 = blockIdx.x * 64;
    int ty = t >> 4, tx = t & 15;
    int ar = t >> 2, ak = (t & 3) << 2;
    int br = t >> 4, bc = (t & 15) << 2;
    float acc[4][4] = {};
    for (int k0 = 0; k0 < K; k0 += 16) {
        float4 a1 = *(const float4*)(A1 + (size_t)(m0 + ar) * K + k0 + ak);
        float4 a2 = *(const float4*)(A2 + (size_t)(m0 + ar) * K + k0 + ak);
        As[ak + 0][ar] = a1.x + a2.x;
        As[ak + 1][ar] = a1.y + a2.y;
        As[ak + 2][ar] = a1.z + a2.z;
        As[ak + 3][ar] = a1.w + a2.w;
        *(float4*)&Bs[br][bc] = *(const float4*)(W + (size_t)(k0 + br) * N + n0 + bc);
        __syncthreads();
#pragma unroll
        for (int k = 0; k < 16; k++) {
            float4 a = *(const float4*)&As[k][ty << 2];
            float4 bq = *(const float4*)&Bs[k][tx << 2];
            float av[4] = {a.x, a.y, a.z, a.w};
            float bv[4] = {bq.x, bq.y, bq.z, bq.w};
#pragma unroll
            for (int i = 0; i < 4; i++)
#pragma unroll
                for (int j = 0; j < 4; j++) acc[i][j] += av[i] * bv[j];
        }
        __syncthreads();
    }
#pragma unroll
    for (int i = 0; i < 4; i++)
#pragma unroll
        for (int j = 0; j < 4; j++) {
            float v = acc[i][j];
            C[(size_t)(m0 + (ty << 2) + i) * N + n0 + (tx << 2) + j] = v > 0.f ? v : 0.f;
        }
}

// Fused pair classifier: gather ci tile -> 3x (GEMM1+bias+relu -> GEMM2+bias).
// 256 threads, TM=32 pairs per block. ~194KB dynamic SMEM.
__global__ void __launch_bounds__(256) classifier_kernel(
    const float* __restrict__ emb, const int* __restrict__ pairs,
    const float* __restrict__ inter,
    const float* __restrict__ W1_0, const float* __restrict__ b1_0,
    const float* __restrict__ W2_0, const float* __restrict__ b2_0,
    const float* __restrict__ W1_1, const float* __restrict__ b1_1,
    const float* __restrict__ W2_1, const float* __restrict__ b2_1,
    const float* __restrict__ W1_2, const float* __restrict__ b1_2,
    const float* __restrict__ W2_2, const float* __restrict__ b2_2,
    float* __restrict__ out) {
    extern __shared__ float sm[];
    float* ci = sm;                       // TM * CIW
    float* hid = sm + TM * CIW;           // TM * CIW
    float* wbuf = sm + 2 * TM * CIW;      // 64*WSW (GEMM1 tile) / W2^T (GEMM2)

    int t = threadIdx.x;
    int gp0 = blockIdx.x * TM;

    // ---- gather ci = [emb[i0]+emb[i1] | inter[i0,i1]] ----
    {
        int r = t >> 3, j8 = t & 7;
        int gp = gp0 + r;
        int b = gp / NP, pi = gp - b * NP;
        int i0 = pairs[((size_t)b * NP + pi) * 2 + 0];
        int i1 = pairs[((size_t)b * NP + pi) * 2 + 1];
        const float4* e0 = (const float4*)(emb + ((size_t)b * NNODE + i0) * DG);
        const float4* e1 = (const float4*)(emb + ((size_t)b * NNODE + i1) * DG);
        const float4* ef = (const float4*)(inter + (((size_t)b * NNODE + i0) * NNODE + i1) * EF);
        float4* crow = (float4*)(ci + r * CIW);
        for (int i = j8; i < 64; i += 8) {
            float4 a = e0[i], c = e1[i];
            a.x += c.x; a.y += c.y; a.z += c.z; a.w += c.w;
            crow[i] = a;
            crow[64 + i] = ef[i];
        }
    }
    __syncthreads();

    const float* W1s[3] = {W1_0, W1_1, W1_2};
    const float* b1s[3] = {b1_0, b1_1, b1_2};
    const float* W2s[3] = {W2_0, W2_1, W2_2};
    const float* b2s[3] = {b2_0, b2_1, b2_2};
    const int outw[3] = {6, 5, 14};
    const int outoff[3] = {0, 6, 11};

    int rg = t >> 5;        // 0..7 -> rows 4*rg..4*rg+3
    int cg = t & 31;        // 0..31
    int c0 = cg << 2;       // cols c0..c0+3 and c0+128..c0+131 within 256-chunk

    for (int head = 0; head < 3; head++) {
        const float* W1 = W1s[head];
        const float* b1 = b1s[head];
        // ---- GEMM1: hid = relu(ci @ W1 + b1), N-chunks of 256, K-chunks of 64 ----
        for (int nc = 0; nc < HIDDEN; nc += 256) {
            float acc[4][8];
#pragma unroll
            for (int i = 0; i < 4; i++)
#pragma unroll
                for (int j = 0; j < 8; j++) acc[i][j] = 0.f;
            for (int kc = 0; kc < DIN; kc += 64) {
                // load W1[kc..kc+63][nc..nc+255] k-major into wbuf
#pragma unroll
                for (int i = 0; i < 16; i++) {
                    int s = t + (i << 8);
                    int k = s >> 6, cq = (s & 63) << 2;
                    *(float4*)&wbuf[k * WSW + cq] =
                        *(const float4*)(W1 + (size_t)(kc + k) * HIDDEN + nc + cq);
                }
                __syncthreads();
                const float* cb = ci + (rg << 2) * CIW + kc;
#pragma unroll 2
                for (int kk = 0; kk < 64; kk += 4) {
                    float ar[4][4];
#pragma unroll
                    for (int i = 0; i < 4; i++)
                        *(float4*)ar[i] = *(const float4*)(cb + i * CIW + kk);
#pragma unroll
                    for (int dk = 0; dk < 4; dk++) {
                        float4 w0 = *(const float4*)&wbuf[(kk + dk) * WSW + c0];
                        float4 w1 = *(const float4*)&wbuf[(kk + dk) * WSW + c0 + 128];
                        float wv[8] = {w0.x, w0.y, w0.z, w0.w, w1.x, w1.y, w1.z, w1.w};
#pragma unroll
                        for (int i = 0; i < 4; i++) {
                            float a = ar[i][dk];
#pragma unroll
                            for (int j = 0; j < 8; j++) acc[i][j] += a * wv[j];
                        }
                    }
                }
                __syncthreads();
            }
            // epilogue: bias + relu -> hid
#pragma unroll
            for (int j = 0; j < 8; j++) {
                int col = nc + c0 + ((j < 4) ? j : (124 + j));
                float bv = b1[col];
#pragma unroll
                for (int i = 0; i < 4; i++) {
                    float v = acc[i][j] + bv;
                    hid[((rg << 2) + i) * CIW + col] = v > 0.f ? v : 0.f;
                }
            }
        }
        __syncthreads();

        // ---- GEMM2: out = hid @ W2 + b2 ----
        int ow = outw[head];
        const float* W2 = W2s[head];
        for (int idx = t; idx < HIDDEN * ow; idx += 256) {
            int k = idx / ow, c = idx - k * ow;
            wbuf[c * CIW + k] = W2[idx];   // W2^T, row stride CIW
        }
        __syncthreads();
        {
            int r = t >> 3, c8 = t & 7;
            const float* hrow = hid + r * CIW;
            int gp = gp0 + r;
            const float* b2 = b2s[head];
            for (int c = c8; c < ow; c += 8) {
                const float* wcol = wbuf + c * CIW;
                float s = 0.f;
#pragma unroll 4
                for (int k = 0; k < HIDDEN; k += 4) {
                    float4 h4 = *(const float4*)(hrow + k);
                    float4 w4 = *(const float4*)(wcol + k);
                    s += h4.x * w4.x + h4.y * w4.y + h4.z * w4.z + h4.w * w4.w;
                }
                out[(size_t)gp * 25 + outoff[head] + c] = s + b2[c];
            }
        }
        __syncthreads();
    }
}

static const int CLS_SMEM = (2 * TM * CIW + 64 * WSW) * 4;   // 198656 bytes

extern "C" void kernel_launch(void* const* d_in, const int* in_sizes, int n_in,
                              void* d_out, int out_size) {
    const float* obj   = (const float*)d_in[0];
    const int*   ei    = (const int*)d_in[1];
    const int*   pairs = (const int*)d_in[2];
    const float* inter = (const float*)d_in[3];
    const float* Wg1   = (const float*)d_in[4];
    const float* Wg2   = (const float*)d_in[5];
    float* out = (float*)d_out;

    float* scratch = nullptr;
    cudaGetSymbolAddress((void**)&scratch, g_scratch);
    float* m1  = scratch;
    float* h   = m1 + (size_t)Bb * NNODE * DIN;
    float* m2  = h  + (size_t)Bb * NNODE * DG;
    float* emb = m2 + (size_t)Bb * NNODE * DG;

    int nm1 = Bb * NNODE * DIN;
    int nm2 = Bb * NNODE * DG;
    zero_kernel<<<(nm1 + 255) / 256, 256>>>(m1, nm1);
    zero_kernel<<<(nm2 + 255) / 256, 256>>>(m2, nm2);

    int scatter_blocks = (Bb * NE * 32) / 256;
    scatter_kernel<<<scatter_blocks, 256>>>(obj, ei, m1, DIN);

    gemm_add_relu<<<dim3(DG / 64, (Bb * NNODE) / 64), 256>>>(m1, obj, Wg1, h,
                                                             Bb * NNODE, DG, DIN);
    scatter_kernel<<<scatter_blocks, 256>>>(h, ei, m2, DG);
    gemm_add_relu<<<dim3(DG / 64, (Bb * NNODE) / 64), 256>>>(m2, h, Wg2, emb,
                                                             Bb * NNODE, DG, DG);

    cudaFuncSetAttribute((const void*)classifier_kernel,
                         cudaFuncAttributeMaxDynamicSharedMemorySize, CLS_SMEM);
    classifier_kernel<<<(Bb * NP) / TM, 256, CLS_SMEM>>>(
        emb, pairs, inter,
        (const float*)d_in[6],  (const float*)d_in[7],  (const float*)d_in[8],  (const float*)d_in[9],
        (const float*)d_in[10], (const float*)d_in[11], (const float*)d_in[12], (const float*)d_in[13],
        (const float*)d_in[14], (const float*)d_in[15], (const float*)d_in[16], (const float*)d_in[17],
        out);
}

// round 12
// speedup vs baseline: 1.0030x; 1.0012x over previous
#include <cuda_runtime.h>

#define Bb 64
#define NNODE 128
#define NE 4096
#define NP 2048
#define DIN 512
#define DG 256
#define EF 256
#define HIDDEN 512

#define TM 32
#define CIW 516     // row stride (floats) for ci / hid tiles
#define WSW 260     // row stride (floats) for W1 k-major tile

// Scratch: m1 [B*N*512], h [B*N*256], m2 [B*N*256], emb [B*N*256]
__device__ float g_scratch[(size_t)Bb * NNODE * DIN + 3 * (size_t)Bb * NNODE * DG];

__global__ void zero_kernel(float* p, int n) {
    int i = blockIdx.x * blockDim.x + threadIdx.x;
    if (i < n) p[i] = 0.f;
}

// m[b, dst] += x[b, src] over edges. One warp per edge.
__global__ void scatter_kernel(const float* __restrict__ x, const int* __restrict__ ei,
                               float* __restrict__ m, int dim) {
    int gw = (blockIdx.x * blockDim.x + threadIdx.x) >> 5;
    int lane = threadIdx.x & 31;
    if (gw >= Bb * NE) return;
    int b = gw / NE;
    int e = gw - b * NE;
    int src = ei[(size_t)b * 2 * NE + e];
    int dst = ei[(size_t)b * 2 * NE + NE + e];
    const float* xs = x + ((size_t)b * NNODE + src) * dim;
    float* md = m + ((size_t)b * NNODE + dst) * dim;
    for (int k = lane; k < dim; k += 32) atomicAdd(md + k, xs[k]);
}

// C = relu((A1 + A2) @ W), A row-major [M,K], W [K,N]. 64x64 tiles, 4x4/thread.
__global__ void __launch_bounds__(256) gemm_add_relu(
    const float* __restrict__ A1, const float* __restrict__ A2,
    const float* __restrict__ W, float* __restrict__ C,
    int M, int N, int K) {
    __shared__ float As[16][68];
    __shared__ float Bs[16][68];
    int t = threadIdx.x;
    int m0 = blockIdx.y * 64, n0 = blockIdx.x * 64;
    int ty = t >> 4, tx = t & 15;
    int ar = t >> 2, ak = (t & 3) << 2;
    int br = t >> 4, bc = (t & 15) << 2;
    float acc[4][4] = {};
    for (int k0 = 0; k0 < K; k0 += 16) {
        float4 a1 = *(const float4*)(A1 + (size_t)(m0 + ar) * K + k0 + ak);
        float4 a2 = *(const float4*)(A2 + (size_t)(m0 + ar) * K + k0 + ak);
        As[ak + 0][ar] = a1.x + a2.x;
        As[ak + 1][ar] = a1.y + a2.y;
        As[ak + 2][ar] = a1.z + a2.z;
        As[ak + 3][ar] = a1.w + a2.w;
        *(float4*)&Bs[br][bc] = *(const float4*)(W + (size_t)(k0 + br) * N + n0 + bc);
        __syncthreads();
#pragma unroll
        for (int k = 0; k < 16; k++) {
            float4 a = *(const float4*)&As[k][ty << 2];
            float4 bq = *(const float4*)&Bs[k][tx << 2];
            float av[4] = {a.x, a.y, a.z, a.w};
            float bv[4] = {bq.x, bq.y, bq.z, bq.w};
#pragma unroll
            for (int i = 0; i < 4; i++)
#pragma unroll
                for (int j = 0; j < 4; j++) acc[i][j] += av[i] * bv[j];
        }
        __syncthreads();
    }
#pragma unroll
    for (int i = 0; i < 4; i++)
#pragma unroll
        for (int j = 0; j < 4; j++) {
            float v = acc[i][j];
            C[(size_t)(m0 + (ty << 2) + i) * N + n0 + (tx << 2) + j] = v > 0.f ? v : 0.f;
        }
}

// Fused pair classifier: gather ci tile -> 3x (GEMM1+bias+relu -> GEMM2+bias).
// 256 threads, TM=32 pairs per block. ~194KB dynamic SMEM.
__global__ void __launch_bounds__(256) classifier_kernel(
    const float* __restrict__ emb, const int* __restrict__ pairs,
    const float* __restrict__ inter,
    const float* __restrict__ W1_0, const float* __restrict__ b1_0,
    const float* __restrict__ W2_0, const float* __restrict__ b2_0,
    const float* __restrict__ W1_1, const float* __restrict__ b1_1,
    const float* __restrict__ W2_1, const float* __restrict__ b2_1,
    const float* __restrict__ W1_2, const float* __restrict__ b1_2,
    const float* __restrict__ W2_2, const float* __restrict__ b2_2,
    float* __restrict__ out) {
    extern __shared__ float sm[];
    float* ci = sm;                       // TM * CIW
    float* hid = sm + TM * CIW;           // TM * CIW
    float* wbuf = sm + 2 * TM * CIW;      // 64*WSW (GEMM1 tile) / W2^T (GEMM2)

    int t = threadIdx.x;
    int gp0 = blockIdx.x * TM;

    // ---- gather ci = [emb[i0]+emb[i1] | inter[i0,i1]] ----
    {
        int r = t >> 3, j8 = t & 7;
        int gp = gp0 + r;
        int b = gp / NP, pi = gp - b * NP;
        int i0 = pairs[((size_t)b * NP + pi) * 2 + 0];
        int i1 = pairs[((size_t)b * NP + pi) * 2 + 1];
        const float4* e0 = (const float4*)(emb + ((size_t)b * NNODE + i0) * DG);
        const float4* e1 = (const float4*)(emb + ((size_t)b * NNODE + i1) * DG);
        const float4* ef = (const float4*)(inter + (((size_t)b * NNODE + i0) * NNODE + i1) * EF);
        float4* crow = (float4*)(ci + r * CIW);
        for (int i = j8; i < 64; i += 8) {
            float4 a = e0[i], c = e1[i];
            a.x += c.x; a.y += c.y; a.z += c.z; a.w += c.w;
            crow[i] = a;
            crow[64 + i] = ef[i];
        }
    }
    __syncthreads();

    const float* W1s[3] = {W1_0, W1_1, W1_2};
    const float* b1s[3] = {b1_0, b1_1, b1_2};
    const float* W2s[3] = {W2_0, W2_1, W2_2};
    const float* b2s[3] = {b2_0, b2_1, b2_2};
    const int outw[3] = {6, 5, 14};
    const int outoff[3] = {0, 6, 11};

    int rg = t >> 5;        // 0..7 -> rows 4*rg..4*rg+3
    int cg = t & 31;        // 0..31
    int c0 = cg << 2;       // cols c0..c0+3 and c0+128..c0+131 within 256-chunk

    for (int head = 0; head < 3; head++) {
        const float* W1 = W1s[head];
        const float* b1 = b1s[head];
        // ---- GEMM1: hid = relu(ci @ W1 + b1), N-chunks of 256, K-chunks of 64 ----
        for (int nc = 0; nc < HIDDEN; nc += 256) {
            float acc[4][8];
#pragma unroll
            for (int i = 0; i < 4; i++)
#pragma unroll
                for (int j = 0; j < 8; j++) acc[i][j] = 0.f;
            for (int kc = 0; kc < DIN; kc += 64) {
                // load W1[kc..kc+63][nc..nc+255] k-major into wbuf
#pragma unroll
                for (int i = 0; i < 16; i++) {
                    int s = t + (i << 8);
                    int k = s >> 6, cq = (s & 63) << 2;
                    *(float4*)&wbuf[k * WSW + cq] =
                        *(const float4*)(W1 + (size_t)(kc + k) * HIDDEN + nc + cq);
                }
                __syncthreads();
                const float* cb = ci + (rg << 2) * CIW + kc;
#pragma unroll 2
                for (int kk = 0; kk < 64; kk += 4) {
                    float ar[4][4];
#pragma unroll
                    for (int i = 0; i < 4; i++)
                        *(float4*)ar[i] = *(const float4*)(cb + i * CIW + kk);
#pragma unroll
                    for (int dk = 0; dk < 4; dk++) {
                        float4 w0 = *(const float4*)&wbuf[(kk + dk) * WSW + c0];
                        float4 w1 = *(const float4*)&wbuf[(kk + dk) * WSW + c0 + 128];
                        float wv[8] = {w0.x, w0.y, w0.z, w0.w, w1.x, w1.y, w1.z, w1.w};
#pragma unroll
                        for (int i = 0; i < 4; i++) {
                            float a = ar[i][dk];
#pragma unroll
                            for (int j = 0; j < 8; j++) acc[i][j] += a * wv[j];
                        }
                    }
                }
                __syncthreads();
            }
            // epilogue: bias + relu -> hid
#pragma unroll
            for (int j = 0; j < 8; j++) {
                int col = nc + c0 + ((j < 4) ? j : (124 + j));
                float bv = b1[col];
#pragma unroll
                for (int i = 0; i < 4; i++) {
                    float v = acc[i][j] + bv;
                    hid[((rg << 2) + i) * CIW + col] = v > 0.f ? v : 0.f;
                }
            }
        }
        __syncthreads();

        // ---- GEMM2: out = hid @ W2 + b2 ----
        int ow = outw[head];
        const float* W2 = W2s[head];
        for (int idx = t; idx < HIDDEN * ow; idx += 256) {
            int k = idx / ow, c = idx - k * ow;
            wbuf[c * CIW + k] = W2[idx];   // W2^T, row stride CIW
        }
        __syncthreads();
        {
            int r = t >> 3, c8 = t & 7;
            const float* hrow = hid + r * CIW;
            int gp = gp0 + r;
            const float* b2 = b2s[head];
            for (int c = c8; c < ow; c += 8) {
                const float* wcol = wbuf + c * CIW;
                float s = 0.f;
#pragma unroll 4
                for (int k = 0; k < HIDDEN; k += 4) {
                    float4 h4 = *(const float4*)(hrow + k);
                    float4 w4 = *(const float4*)(wcol + k);
                    s += h4.x * w4.x + h4.y * w4.y + h4.z * w4.z + h4.w * w4.w;
                }
                out[(size_t)gp * 25 + outoff[head] + c] = s + b2[c];
            }
        }
        __syncthreads();
    }
}

static const int CLS_SMEM = (2 * TM * CIW + 64 * WSW) * 4;   // 198656 bytes

extern "C" void kernel_launch(void* const* d_in, const int* in_sizes, int n_in,
                              void* d_out, int out_size) {
    const float* obj   = (const float*)d_in[0];
    const int*   ei    = (const int*)d_in[1];
    const int*   pairs = (const int*)d_in[2];
    const float* inter = (const float*)d_in[3];
    const float* Wg1   = (const float*)d_in[4];
    const float* Wg2   = (const float*)d_in[5];
    float* out = (float*)d_out;

    float* scratch = nullptr;
    cudaGetSymbolAddress((void**)&scratch, g_scratch);
    float* m1  = scratch;
    float* h   = m1 + (size_t)Bb * NNODE * DIN;
    float* m2  = h  + (size_t)Bb * NNODE * DG;
    float* emb = m2 + (size_t)Bb * NNODE * DG;

    int nm1 = Bb * NNODE * DIN;
    int nm2 = Bb * NNODE * DG;
    zero_kernel<<<(nm1 + 255) / 256, 256>>>(m1, nm1);
    zero_kernel<<<(nm2 + 255) / 256, 256>>>(m2, nm2);

    int scatter_blocks = (Bb * NE * 32) / 256;
    scatter_kernel<<<scatter_blocks, 256>>>(obj, ei, m1, DIN);

    gemm_add_relu<<<dim3(DG / 64, (Bb * NNODE) / 64), 256>>>(m1, obj, Wg1, h,
                                                             Bb * NNODE, DG, DIN);
    scatter_kernel<<<scatter_blocks, 256>>>(h, ei, m2, DG);
    gemm_add_relu<<<dim3(DG / 64, (Bb * NNODE) / 64), 256>>>(m2, h, Wg2, emb,
                                                             Bb * NNODE, DG, DG);

    cudaFuncSetAttribute((const void*)classifier_kernel,
                         cudaFuncAttributeMaxDynamicSharedMemorySize, CLS_SMEM);
    classifier_kernel<<<(Bb * NP) / TM, 256, CLS_SMEM>>>(
        emb, pairs, inter,
        (const float*)d_in[6],  (const float*)d_in[7],  (const float*)d_in[8],  (const float*)d_in[9],
        (const float*)d_in[10], (const float*)d_in[11], (const float*)d_in[12], (const float*)d_in[13],
        (const float*)d_in[14], (const float*)d_in[15], (const float*)d_in[16], (const float*)d_in[17],
        out);
}